// round 2
// baseline (speedup 1.0000x reference)
#include <cuda_runtime.h>
#include <cuda_fp16.h>
#include <cstdint>

#define M_TOK 16384
#define KF    5760
#define KR    32
#define KEXT  5792
#define NOUT  640
#define NGROUP 90

// Scratch (device globals: allocation-free per harness rules)
__device__ __half g_A[(size_t)M_TOK * KEXT];   // [xq | t]  ~190MB
__device__ __half g_B[(size_t)KEXT * NOUT];    // [wdeq ; pu]
__device__ __half g_pd[(size_t)KF * KR];       // proj_down f16

// ---------------- helpers ----------------
__device__ __forceinline__ uint32_t smem_u32(const void* p) {
    return (uint32_t)__cvta_generic_to_shared(p);
}
__device__ __forceinline__ void ldmx4(uint32_t& r0, uint32_t& r1, uint32_t& r2, uint32_t& r3, uint32_t a) {
    asm volatile("ldmatrix.sync.aligned.m8n8.x4.shared.b16 {%0,%1,%2,%3}, [%4];"
                 : "=r"(r0), "=r"(r1), "=r"(r2), "=r"(r3) : "r"(a));
}
__device__ __forceinline__ void ldmx4t(uint32_t& r0, uint32_t& r1, uint32_t& r2, uint32_t& r3, uint32_t a) {
    asm volatile("ldmatrix.sync.aligned.m8n8.x4.trans.shared.b16 {%0,%1,%2,%3}, [%4];"
                 : "=r"(r0), "=r"(r1), "=r"(r2), "=r"(r3) : "r"(a));
}
__device__ __forceinline__ void mma16816(float c[4], const uint32_t a[4], const uint32_t b[2]) {
    asm volatile("mma.sync.aligned.m16n8k16.row.col.f32.f16.f16.f32 "
        "{%0,%1,%2,%3}, {%4,%5,%6,%7}, {%8,%9}, {%0,%1,%2,%3};"
        : "+f"(c[0]), "+f"(c[1]), "+f"(c[2]), "+f"(c[3])
        : "r"(a[0]), "r"(a[1]), "r"(a[2]), "r"(a[3]), "r"(b[0]), "r"(b[1]));
}
__device__ __forceinline__ void cp16(void* dst_smem, const void* src_g) {
    uint32_t d = smem_u32(dst_smem);
    asm volatile("cp.async.cg.shared.global [%0], [%1], 16;" :: "r"(d), "l"(src_g));
}

// ---------------- K0: build B_ext (wdeq | pu rows) + pd f16 ----------------
__global__ void k_prep(const float* __restrict__ qw, const float* __restrict__ ws,
                       const float* __restrict__ pu, const float* __restrict__ pd) {
    const int totB = KEXT * NOUT;            // 3,706,880
    const int tot  = totB + KF * KR;         // + 184,320
    for (int idx = blockIdx.x * blockDim.x + threadIdx.x; idx < tot; idx += gridDim.x * blockDim.x) {
        if (idx < totB) {
            int k = idx / NOUT, n = idx - k * NOUT;
            float v;
            if (k < KF) v = qw[(size_t)k * NOUT + n] * ws[(size_t)(k >> 6) * NOUT + n];
            else        v = pu[(size_t)(k - KF) * NOUT + n];
            g_B[idx] = __float2half(v);
        } else {
            int j = idx - totB;
            g_pd[j] = __float2half(pd[j]);
        }
    }
}

// ---------------- K1: quantize x -> g_A[:, 0:5760] (f16) ----------------
// One block per token row; warp-per-group (group=64 floats, 2 per lane).
__global__ void __launch_bounds__(256) k_quant(const float* __restrict__ x) {
    const int row  = blockIdx.x;
    const int warp = threadIdx.x >> 5, lane = threadIdx.x & 31;
    const float* xr = x + (size_t)row * KF;
    __half* ar = g_A + (size_t)row * KEXT;
    for (int g = warp; g < NGROUP; g += 8) {
        float2 v = *(const float2*)(xr + g * 64 + lane * 2);
        float m = fmaxf(fabsf(v.x), fabsf(v.y));
        #pragma unroll
        for (int off = 16; off > 0; off >>= 1)
            m = fmaxf(m, __shfl_xor_sync(0xffffffffu, m, off));
        float s = fmaxf(__fdiv_rn(m, 7.0f), 1e-6f);
        float q0 = fminf(fmaxf(rintf(__fdiv_rn(v.x, s)), -8.0f), 7.0f);
        float q1 = fminf(fmaxf(rintf(__fdiv_rn(v.y, s)), -8.0f), 7.0f);
        *(__half2*)(ar + g * 64 + lane * 2) = __floats2half2_rn(q0 * s, q1 * s);
    }
}

// ---------------- K2: t = x_f16 @ pd_f16  -> g_A[:, 5760:5792] ----------------
// CTA: 64 rows, 128 threads (4 warps, each m16 x n32), K loop 90 x 64.
__global__ void __launch_bounds__(128) k_lowrank(const float* __restrict__ x) {
    __shared__ __half xs[64 * 72];   // 64 rows x 64 halves, pad->72
    __shared__ __half pds[64 * 40];  // 64 rows x 32 halves, pad->40
    const int tid = threadIdx.x;
    const int lane = tid & 31, warp = tid >> 5;
    const int m0 = blockIdx.x * 64;

    float acc[4][4];
    #pragma unroll
    for (int i = 0; i < 4; i++)
        #pragma unroll
        for (int j = 0; j < 4; j++) acc[i][j] = 0.f;

    for (int k0 = 0; k0 < KF; k0 += 64) {
        #pragma unroll
        for (int i = 0; i < 8; i++) {
            int f4 = tid + i * 128;                 // 0..1023
            int r = f4 >> 4, c4 = f4 & 15;
            float4 v = *(const float4*)(x + (size_t)(m0 + r) * KF + k0 + c4 * 4);
            *(__half2*)(xs + r * 72 + c4 * 4)     = __floats2half2_rn(v.x, v.y);
            *(__half2*)(xs + r * 72 + c4 * 4 + 2) = __floats2half2_rn(v.z, v.w);
        }
        #pragma unroll
        for (int p = 0; p < 2; p++) {
            int t = tid + p * 128;
            int r = t >> 2, c = (t & 3) * 8;
            *(uint4*)(pds + r * 40 + c) = *(const uint4*)(g_pd + (size_t)(k0 + r) * KR + c);
        }
        __syncthreads();

        #pragma unroll
        for (int kk = 0; kk < 4; kk++) {
            uint32_t a[4];
            ldmx4(a[0], a[1], a[2], a[3],
                  smem_u32(xs + (warp * 16 + (lane & 15)) * 72 + kk * 16 + (lane >> 4) * 8));
            uint32_t b[4][2];
            #pragma unroll
            for (int np = 0; np < 2; np++) {
                uint32_t r0, r1, r2, r3;
                ldmx4t(r0, r1, r2, r3,
                       smem_u32(pds + (kk * 16 + (lane & 15)) * 40 + np * 16 + (lane >> 4) * 8));
                b[np * 2][0] = r0; b[np * 2][1] = r1;
                b[np * 2 + 1][0] = r2; b[np * 2 + 1][1] = r3;
            }
            #pragma unroll
            for (int ni = 0; ni < 4; ni++) mma16816(acc[ni], a, b[ni]);
        }
        __syncthreads();
    }
    #pragma unroll
    for (int ni = 0; ni < 4; ni++) {
        int c = ni * 8 + (lane & 3) * 2;
        int r = m0 + warp * 16 + (lane >> 2);
        g_A[(size_t)r * KEXT + KF + c]           = __float2half(acc[ni][0]);
        g_A[(size_t)r * KEXT + KF + c + 1]       = __float2half(acc[ni][1]);
        g_A[(size_t)(r + 8) * KEXT + KF + c]     = __float2half(acc[ni][2]);
        g_A[(size_t)(r + 8) * KEXT + KF + c + 1] = __float2half(acc[ni][3]);
    }
}

// ---------------- K3: main GEMM C = A_ext @ B_ext + bias, transposed store ----------------
// BM=128 BN=128 BK=32, 4-stage cp.async, 256 threads, warp tile 64x32.
#define ASTRIDE 40
#define BSTRIDE 136
#define A_STAGE (128 * ASTRIDE)
#define B_STAGE (32 * BSTRIDE)
#define SMEM_HALVES (4 * A_STAGE + 4 * B_STAGE)
#define SMEM_BYTES (SMEM_HALVES * 2)

__global__ void __launch_bounds__(256, 2) k_gemm(const float* __restrict__ bias, float* __restrict__ out) {
    extern __shared__ __half smem[];
    __half* As = smem;
    __half* Bs = smem + 4 * A_STAGE;

    const int tid = threadIdx.x;
    const int lane = tid & 31, warp = tid >> 5;
    const int wm = warp >> 2, wn = warp & 3;       // 2 x 4 warp grid
    const int m0 = blockIdx.y * 128;
    const int n0 = blockIdx.x * 128;

    float acc[4][4][4];
    #pragma unroll
    for (int i = 0; i < 4; i++)
        #pragma unroll
        for (int j = 0; j < 4; j++)
            #pragma unroll
            for (int k = 0; k < 4; k++) acc[i][j][k] = 0.f;

    auto issue = [&](int kt) {
        int s = kt & 3;
        const __half* Ag = g_A + (size_t)m0 * KEXT + kt * 32;
        __half* Asd = As + s * A_STAGE;
        #pragma unroll
        for (int p = 0; p < 2; p++) {
            int cid = tid + p * 256;
            int r = cid >> 2, c4 = cid & 3;
            cp16(Asd + r * ASTRIDE + c4 * 8, Ag + (size_t)r * KEXT + c4 * 8);
        }
        const __half* Bg = g_B + (size_t)(kt * 32) * NOUT + n0;
        __half* Bsd = Bs + s * B_STAGE;
        #pragma unroll
        for (int p = 0; p < 2; p++) {
            int cid = tid + p * 256;
            int r = cid >> 4, c16 = cid & 15;
            cp16(Bsd + r * BSTRIDE + c16 * 8, Bg + (size_t)r * NOUT + c16 * 8);
        }
        asm volatile("cp.async.commit_group;");
    };

    const int KT = KEXT / 32;  // 181
    issue(0); issue(1); issue(2);

    for (int kt = 0; kt < KT; kt++) {
        asm volatile("cp.async.wait_group 2;");
        __syncthreads();
        if (kt + 3 < KT) issue(kt + 3);
        else asm volatile("cp.async.commit_group;");

        int s = kt & 3;
        const __half* Asd = As + s * A_STAGE;
        const __half* Bsd = Bs + s * B_STAGE;
        #pragma unroll
        for (int kk = 0; kk < 2; kk++) {
            uint32_t a[4][4];
            #pragma unroll
            for (int mi = 0; mi < 4; mi++)
                ldmx4(a[mi][0], a[mi][1], a[mi][2], a[mi][3],
                      smem_u32(Asd + (wm * 64 + mi * 16 + (lane & 15)) * ASTRIDE + kk * 16 + (lane >> 4) * 8));
            uint32_t b[4][2];
            #pragma unroll
            for (int np = 0; np < 2; np++) {
                uint32_t r0, r1, r2, r3;
                ldmx4t(r0, r1, r2, r3,
                       smem_u32(Bsd + (kk * 16 + (lane & 15)) * BSTRIDE + wn * 32 + np * 16 + (lane >> 4) * 8));
                b[np * 2][0] = r0; b[np * 2][1] = r1;
                b[np * 2 + 1][0] = r2; b[np * 2 + 1][1] = r3;
            }
            #pragma unroll
            for (int mi = 0; mi < 4; mi++)
                #pragma unroll
                for (int ni = 0; ni < 4; ni++)
                    mma16816(acc[mi][ni], a[mi], b[ni]);
        }
    }

    // Epilogue: bias + transposed scatter store. out[((batch*640 + c) << 12) + l], m = batch*4096 + l
    #pragma unroll
    for (int ni = 0; ni < 4; ni++) {
        int cg = n0 + wn * 32 + ni * 8 + (lane & 3) * 2;
        float b0 = __ldg(bias + cg), b1 = __ldg(bias + cg + 1);
        #pragma unroll
        for (int mi = 0; mi < 4; mi++) {
            int r = m0 + wm * 64 + mi * 16 + (lane >> 2);
            int batch = r >> 12, l = r & 4095;
            size_t base = ((size_t)(batch * NOUT + cg) << 12) + l;
            out[base]            = acc[mi][ni][0] + b0;
            out[base + 4096]     = acc[mi][ni][1] + b1;
            out[base + 8]        = acc[mi][ni][2] + b0;
            out[base + 4096 + 8] = acc[mi][ni][3] + b1;
        }
    }
}

// ---------------- launch ----------------
extern "C" void kernel_launch(void* const* d_in, const int* in_sizes, int n_in,
                              void* d_out, int out_size) {
    const float* x    = (const float*)d_in[0];
    const float* qw   = (const float*)d_in[1];
    const float* ws   = (const float*)d_in[2];
    const float* pd   = (const float*)d_in[3];
    const float* pu   = (const float*)d_in[4];
    const float* bias = (const float*)d_in[5];
    float* out = (float*)d_out;

    cudaFuncSetAttribute(k_gemm, cudaFuncAttributeMaxDynamicSharedMemorySize, SMEM_BYTES);

    k_prep<<<4096, 256>>>(qw, ws, pu, pd);
    k_quant<<<M_TOK, 256>>>(x);
    k_lowrank<<<M_TOK / 64, 128>>>(x);
    dim3 g3(NOUT / 128, M_TOK / 128);
    k_gemm<<<g3, 256, SMEM_BYTES>>>(bias, out);
}